// round 16
// baseline (speedup 1.0000x reference)
#include <cuda_runtime.h>

// ---------------------------------------------------------------------------
// PromptedAttention: B=8, H=W=32, C=768, heads=12, hd=64, nt=8, N=1032
// Round 16: tail-tile warp skip + pre-converted Q fragments in attention;
// float4 q-loads in rel_kernel (ld=68). Otherwise identical to R15.
// ---------------------------------------------------------------------------

#define BATCH     8
#define HEADS     12
#define HD        64
#define C_DIM     768
#define NT        8
#define HW        1024
#define NSEQ      1032
#define BHN       96
#define MROWS     8256
#define QKV_N     2304
#define XOUT_ELEMS 6291456

__device__ float g_q[BHN * NSEQ * HD];
__device__ float g_k[BHN * NSEQ * HD];
__device__ float g_v[BHN * NSEQ * HD];
__device__ float g_relh[BHN * 32 * 32 * 32];
__device__ float g_relw[BHN * 32 * 32 * 32];
__device__ float g_ctx[MROWS * C_DIM];
__device__ float g_xs[MROWS * C_DIM];
__device__ float g_wq[C_DIM * QKV_N];
__device__ float g_wp[C_DIM * C_DIM];

__device__ __forceinline__ unsigned f2tf(float f) {
    unsigned u;
    asm("cvt.rna.tf32.f32 %0, %1;" : "=r"(u) : "f"(f));
    return u;
}
__device__ __forceinline__ float f2tff(float f) { return __uint_as_float(f2tf(f)); }

__device__ __forceinline__ void mma8(float* c, const unsigned* a, const unsigned* b) {
    asm volatile(
        "mma.sync.aligned.m16n8k8.row.col.f32.tf32.tf32.f32 "
        "{%0,%1,%2,%3}, {%4,%5,%6,%7}, {%8,%9}, {%0,%1,%2,%3};\n"
        : "+f"(c[0]), "+f"(c[1]), "+f"(c[2]), "+f"(c[3])
        : "r"(a[0]), "r"(a[1]), "r"(a[2]), "r"(a[3]), "r"(b[0]), "r"(b[1]));
}

__device__ __forceinline__ unsigned smem_u32(const void* p) {
    return (unsigned)__cvta_generic_to_shared(p);
}
__device__ __forceinline__ void cpasync16(unsigned dst, const void* src, bool pred) {
    asm volatile("cp.async.cg.shared.global [%0], [%1], 16, %2;\n"
                 :: "r"(dst), "l"(src), "r"(pred ? 16 : 0));
}
#define CP_COMMIT() asm volatile("cp.async.commit_group;\n" ::: "memory")
#define CP_WAIT(N)  asm volatile("cp.async.wait_group %0;\n" :: "n"(N) : "memory")

#define A_LD 36
#define B_LD 136
#define A_STG (128 * A_LD)
#define B_STG (32 * B_LD)
#define GEMM_SM_BYTES (2 * (A_STG + B_STG) * 4)   // 71680

// ---------------------------------------------------------------------------
// K0a: build rounded concat g_xs.
// ---------------------------------------------------------------------------
__global__ __launch_bounds__(256) void prep_xs_kernel(
    const float* __restrict__ x, const float* __restrict__ vp)
{
    const int F4 = C_DIM / 4;
    const int total = MROWS * F4;
    for (int idx = blockIdx.x * 256 + threadIdx.x; idx < total;
         idx += gridDim.x * 256) {
        int row = idx / F4;
        int f4 = idx - row * F4;
        int b = row / NSEQ, n = row % NSEQ;
        const float4* src = (n < NT)
            ? (const float4*)(vp + ((size_t)b * NT + n) * C_DIM)
            : (const float4*)(x + ((size_t)b * HW + (n - NT)) * C_DIM);
        float4 t = src[f4];
        float4 o;
        o.x = f2tff(t.x); o.y = f2tff(t.y); o.z = f2tff(t.z); o.w = f2tff(t.w);
        ((float4*)g_xs)[idx] = o;
    }
}

__global__ __launch_bounds__(256) void prep_w_kernel(
    const float* __restrict__ wq, const float* __restrict__ wp)
{
    const int T1 = C_DIM * QKV_N / 4;
    const int T2 = C_DIM * C_DIM / 4;
    for (int idx = blockIdx.x * 256 + threadIdx.x; idx < T1 + T2;
         idx += gridDim.x * 256) {
        float4 t;
        float4* dst;
        if (idx < T1) { t = ((const float4*)wq)[idx]; dst = (float4*)g_wq + idx; }
        else { t = ((const float4*)wp)[idx - T1]; dst = (float4*)g_wp + (idx - T1); }
        float4 o;
        o.x = f2tff(t.x); o.y = f2tff(t.y); o.z = f2tff(t.z); o.w = f2tff(t.w);
        *dst = o;
    }
}

// ---------------------------------------------------------------------------
// K1: fused QKV GEMM, BK=32, 2-stage cp.async, dynamic smem.
// ---------------------------------------------------------------------------
__global__ __launch_bounds__(256) void qkv_mma_kernel(const float* __restrict__ bias)
{
    extern __shared__ float dynsm[];
    float* Asb = dynsm;
    float* Bsb = dynsm + 2 * A_STG;

    const int m0 = blockIdx.y * 128;
    const int n0 = blockIdx.x * 128;
    const int tid = threadIdx.x;
    const int wid = tid >> 5, lane = tid & 31;
    const int g = lane >> 2, tig = lane & 3;
    const int wm = wid >> 1, wn = wid & 1;

    const int aRow = tid >> 1;
    const int aK   = (tid & 1) * 16;
    const int am   = m0 + aRow;
    const bool av  = (am < MROWS);
    const float* arp = g_xs + (size_t)(av ? am : 0) * C_DIM;

    const int bk = tid >> 5;
    const int bn = (tid & 31) * 4;

    float c[2][8][4];
#pragma unroll
    for (int mt = 0; mt < 2; ++mt)
#pragma unroll
        for (int nt = 0; nt < 8; ++nt)
#pragma unroll
            for (int j = 0; j < 4; ++j) c[mt][nt][j] = 0.f;

    auto load_stage = [&](int s, int k0) {
        unsigned ad = smem_u32(&Asb[s * A_STG + aRow * A_LD + aK]);
        unsigned bd = smem_u32(&Bsb[s * B_STG + bk * B_LD + bn]);
#pragma unroll
        for (int i = 0; i < 4; ++i)
            cpasync16(ad + 16 * i, arp + k0 + aK + 4 * i, av);
#pragma unroll
        for (int i = 0; i < 4; ++i)
            cpasync16(bd + (8 * i) * B_LD * 4,
                      g_wq + (size_t)(k0 + bk + 8 * i) * QKV_N + n0 + bn, true);
        CP_COMMIT();
    };

    const int NKT = C_DIM / 32;
    load_stage(0, 0);

    for (int kt = 0; kt < NKT; ++kt) {
        int s = kt & 1;
        if (kt + 1 < NKT) { load_stage(s ^ 1, (kt + 1) * 32); CP_WAIT(1); }
        else              { CP_WAIT(0); }
        __syncthreads();

        const unsigned* Au = (const unsigned*)(Asb + s * A_STG);
        const unsigned* Bu = (const unsigned*)(Bsb + s * B_STG);
#pragma unroll
        for (int ks = 0; ks < 4; ++ks) {
            unsigned a[2][4];
#pragma unroll
            for (int mt = 0; mt < 2; ++mt) {
                int mr = wm * 32 + mt * 16;
                a[mt][0] = Au[(mr + g    ) * A_LD + ks * 8 + tig];
                a[mt][1] = Au[(mr + g + 8) * A_LD + ks * 8 + tig];
                a[mt][2] = Au[(mr + g    ) * A_LD + ks * 8 + tig + 4];
                a[mt][3] = Au[(mr + g + 8) * A_LD + ks * 8 + tig + 4];
            }
            unsigned b[8][2];
#pragma unroll
            for (int nt = 0; nt < 8; ++nt) {
                int nc = wn * 64 + nt * 8 + g;
                b[nt][0] = Bu[(ks * 8 + tig    ) * B_LD + nc];
                b[nt][1] = Bu[(ks * 8 + tig + 4) * B_LD + nc];
            }
#pragma unroll
            for (int mt = 0; mt < 2; ++mt)
#pragma unroll
                for (int nt = 0; nt < 8; ++nt) mma8(c[mt][nt], a[mt], b[nt]);
        }
        __syncthreads();
    }

    float* bufs[3] = {g_q, g_k, g_v};
#pragma unroll
    for (int nt = 0; nt < 8; ++nt) {
        int col = n0 + wn * 64 + nt * 8 + tig * 2;
        int which = col / C_DIM;
        int c2 = col % C_DIM;
        int head = c2 >> 6, db = c2 & 63;
        float b0v = bias[col], b1v = bias[col + 1];
        float* buf = bufs[which];
#pragma unroll
        for (int mt = 0; mt < 2; ++mt) {
#pragma unroll
            for (int h = 0; h < 2; ++h) {
                int m = m0 + wm * 32 + mt * 16 + g + h * 8;
                if (m >= MROWS) continue;
                int bb = m / NSEQ, nn = m % NSEQ;
                float* dst = buf + (size_t)bb * (HEADS * NSEQ * HD)
                                 + (size_t)head * (NSEQ * HD)
                                 + (size_t)nn * HD + db;
                float2 v;
                v.x = f2tff(c[mt][nt][h * 2 + 0] + b0v);
                v.y = f2tff(c[mt][nt][h * 2 + 1] + b1v);
                *(float2*)dst = v;
            }
        }
    }
}

// ---------------------------------------------------------------------------
// K2: rel bias GEMMs — 4 bh/block, shared R tile; float4 q (ld=68) + rv loads.
// ---------------------------------------------------------------------------
__global__ __launch_bounds__(256) void rel_kernel(
    const float* __restrict__ rph, const float* __restrict__ rpw)
{
    __shared__ float qs[4][32 * 68];  // ld=68 -> row*68+c4 16B-aligned
    __shared__ float RsT[64 * 36];    // [c][k], ld=36 -> float4 aligned

    const int bh0 = blockIdx.y * 4;
    const int idx0 = blockIdx.x;
    const int variant = blockIdx.z;
    const int tid = threadIdx.x;

    const float* rp = (variant == 0) ? rph : rpw;
#pragma unroll
    for (int it = 0; it < 8; ++it) {
        int idx = tid + it * 256;       // 2048
        int k = idx >> 6, c = idx & 63;
        RsT[c * 36 + k] = rp[(size_t)(idx0 - k + 31) * HD + c];
    }
#pragma unroll
    for (int it = 0; it < 32; ++it) {
        int idx = tid + it * 256;       // 8192
        int grp = idx >> 11;
        int w = idx & 2047;
        int r = w >> 6, c = w & 63;
        int bh = bh0 + grp;
        int n = (variant == 0) ? (NT + idx0 * 32 + r) : (NT + r * 32 + idx0);
        qs[grp][r * 68 + c] = g_q[((size_t)bh * NSEQ + n) * HD + c];
    }
    __syncthreads();

    const int grp = tid >> 6;
    const int stid = tid & 63;
    const int bh = bh0 + grp;
    const int tr = stid >> 3;
    const int tk = stid & 7;
    const float* qsg = qs[grp];

    float acc[4][4];
#pragma unroll
    for (int i = 0; i < 4; ++i)
#pragma unroll
        for (int j = 0; j < 4; ++j) acc[i][j] = 0.f;

#pragma unroll 2
    for (int c4 = 0; c4 < 64; c4 += 4) {
        float4 qv[4];
#pragma unroll
        for (int i = 0; i < 4; ++i)
            qv[i] = *(const float4*)&qsg[(tr * 4 + i) * 68 + c4];
        float4 rv0 = *(const float4*)&RsT[(c4 + 0) * 36 + tk * 4];
        float4 rv1 = *(const float4*)&RsT[(c4 + 1) * 36 + tk * 4];
        float4 rv2 = *(const float4*)&RsT[(c4 + 2) * 36 + tk * 4];
        float4 rv3 = *(const float4*)&RsT[(c4 + 3) * 36 + tk * 4];
#pragma unroll
        for (int i = 0; i < 4; ++i) {
            acc[i][0] += qv[i].x * rv0.x; acc[i][1] += qv[i].x * rv0.y;
            acc[i][2] += qv[i].x * rv0.z; acc[i][3] += qv[i].x * rv0.w;
            acc[i][0] += qv[i].y * rv1.x; acc[i][1] += qv[i].y * rv1.y;
            acc[i][2] += qv[i].y * rv1.z; acc[i][3] += qv[i].y * rv1.w;
            acc[i][0] += qv[i].z * rv2.x; acc[i][1] += qv[i].z * rv2.y;
            acc[i][2] += qv[i].z * rv2.z; acc[i][3] += qv[i].z * rv2.w;
            acc[i][0] += qv[i].w * rv3.x; acc[i][1] += qv[i].w * rv3.y;
            acc[i][2] += qv[i].w * rv3.z; acc[i][3] += qv[i].w * rv3.w;
        }
    }

    float* outb = (variant == 0) ? g_relh : g_relw;
#pragma unroll
    for (int i = 0; i < 4; ++i) {
        int row = tr * 4 + i;
        size_t base = (variant == 0)
            ? ((((size_t)bh * 32 + idx0) * 32 + row) * 32)
            : ((((size_t)bh * 32 + row) * 32 + idx0) * 32);
        float4 v;
        v.x = acc[i][0]; v.y = acc[i][1]; v.z = acc[i][2]; v.w = acc[i][3];
        *(float4*)(outb + base + tk * 4) = v;
    }
}

// ---------------------------------------------------------------------------
// K3: FA2 attention: register tf32 Q fragments, cp.async K/V double buffer,
// paired rel-bias loads, tail-tile warp skip.
// ---------------------------------------------------------------------------
#define KS_STG (64 * 68)
#define VS_STG (64 * 72)
#define ATT_SM_FLOATS (2 * KS_STG + 2 * VS_STG + 2 * 128 * 32)
#define ATT_SM_BYTES  (ATT_SM_FLOATS * 4)   // 104448

__global__ __launch_bounds__(256, 2) void attn_mma_kernel()
{
    extern __shared__ float sm[];
    float* Ks  = sm;                    // [2][64][68]
    float* Vs  = Ks + 2 * KS_STG;       // [2][64][72]
    float* rhs = Vs + 2 * VS_STG;       // [128][32]
    float* rws = rhs + 128 * 32;        // [128][32]

    const int tid = threadIdx.x;
    const int wid = tid >> 5, lane = tid & 31;
    const int g = lane >> 2, tig = lane & 3;
    const int bh = blockIdx.y;
    const int b = bh / HEADS, head = bh % HEADS;
    const int q0 = blockIdx.x * 128;

    const float* qbase = g_q + (size_t)bh * NSEQ * HD;
    const float* kbase = g_k + (size_t)bh * NSEQ * HD;
    const float* vbase = g_v + (size_t)bh * NSEQ * HD;

    const int r0 = wid * 16 + g;
    const int r1 = r0 + 8;
    const int qg0 = q0 + r0, qg1 = q0 + r1;
    const bool warp_active = (q0 + wid * 16 < NSEQ);   // warp-uniform

    const int lr  = tid >> 4;
    const int ld4 = (tid & 15) * 4;
    auto load_kv = [&](int s, int k0) {
        float* Ksb = Ks + s * KS_STG;
        float* Vsb = Vs + s * VS_STG;
#pragma unroll
        for (int t = 0; t < 4; ++t) {
            int r = lr + t * 16;
            int kg = k0 + r;
            bool pv = (kg < NSEQ);
            const float* ksrc = kbase + (size_t)(pv ? kg : 0) * HD + ld4;
            const float* vsrc = vbase + (size_t)(pv ? kg : 0) * HD + ld4;
            cpasync16(smem_u32(&Ksb[r * 68 + ld4]), ksrc, pv);
            cpasync16(smem_u32(&Vsb[r * 72 + ld4]), vsrc, pv);
        }
        CP_COMMIT();
    };

    load_kv(0, 0);

    // Q fragments from gmem, x0.125, pre-converted to tf32 once
    unsigned qa[8][4];
    {
        const bool v0 = (qg0 < NSEQ), v1 = (qg1 < NSEQ);
        const float* qr0 = qbase + (size_t)(v0 ? qg0 : 0) * HD;
        const float* qr1 = qbase + (size_t)(v1 ? qg1 : 0) * HD;
#pragma unroll
        for (int ks = 0; ks < 8; ++ks) {
            qa[ks][0] = f2tf(v0 ? qr0[ks * 8 + tig]     * 0.125f : 0.f);
            qa[ks][1] = f2tf(v1 ? qr1[ks * 8 + tig]     * 0.125f : 0.f);
            qa[ks][2] = f2tf(v0 ? qr0[ks * 8 + tig + 4] * 0.125f : 0.f);
            qa[ks][3] = f2tf(v1 ? qr1[ks * 8 + tig + 4] * 0.125f : 0.f);
        }
    }

#pragma unroll
    for (int it = 0; it < 4; ++it) {
        int idx = tid + it * 256;
        int r = idx >> 3, c4 = (idx & 7) * 4;
        int qg = q0 + r;
        float4 hv = make_float4(0.f, 0.f, 0.f, 0.f), wv = hv;
        if (qg >= NT && qg < NSEQ) {
            int pix = qg - NT;
            int hq = pix >> 5, wq = pix & 31;
            size_t rbase = (((size_t)bh * 32 + hq) * 32 + wq) * 32;
            hv = *(const float4*)(g_relh + rbase + c4);
            wv = *(const float4*)(g_relw + rbase + c4);
        }
        *(float4*)&rhs[r * 32 + c4] = hv;
        *(float4*)&rws[r * 32 + c4] = wv;
    }

    float m0r = -3.0e38f, l0r = 0.f;
    float m1r = -3.0e38f, l1r = 0.f;
    float oc[8][4];
#pragma unroll
    for (int nt = 0; nt < 8; ++nt)
#pragma unroll
        for (int j = 0; j < 4; ++j) oc[nt][j] = 0.f;

    __syncthreads();

    const int srcA = (lane & ~3) | (tig >> 1);
    const int srcB = srcA + 2;
    const bool odd = (tig & 1);
    const bool qp0 = (qg0 >= NT), qp1 = (qg1 >= NT);

    const int NIT = (NSEQ + 63) / 64;
    for (int itk = 0; itk < NIT; ++itk) {
        int s = itk & 1;
        int k0 = itk * 64;
        if (itk + 1 < NIT) { load_kv(s ^ 1, k0 + 64); CP_WAIT(1); }
        else               { CP_WAIT(0); }
        __syncthreads();

        if (warp_active) {
            const unsigned* Ku = (const unsigned*)(Ks + s * KS_STG);
            const unsigned* Vu = (const unsigned*)(Vs + s * VS_STG);

            float sc[8][4];
#pragma unroll
            for (int nt = 0; nt < 8; ++nt)
#pragma unroll
                for (int j = 0; j < 4; ++j) sc[nt][j] = 0.f;
#pragma unroll
            for (int ks = 0; ks < 8; ++ks) {
#pragma unroll
                for (int nt = 0; nt < 8; ++nt) {
                    unsigned bb[2];
                    int key = nt * 8 + g;
                    bb[0] = Ku[key * 68 + ks * 8 + tig];
                    bb[1] = Ku[key * 68 + ks * 8 + tig + 4];
                    mma8(sc[nt], qa[ks], bb);
                }
            }

            float tm0 = -3.0e38f, tm1 = -3.0e38f;
#pragma unroll
            for (int nt = 0; nt < 8; ++nt) {
                int jg = k0 + nt * 8 + tig * 2;     // even
                float v00 = sc[nt][0], v01 = sc[nt][1];
                float v10 = sc[nt][2], v11 = sc[nt][3];
                if (jg >= NSEQ) {
                    v00 = v01 = v10 = v11 = -1e30f;
                } else if (jg < NT) {
                    if (qp0) { v00 -= 100.f; v01 -= 100.f; }
                    if (qp1) { v10 -= 100.f; v11 -= 100.f; }
                } else {
                    int pj = jg - NT;
                    int hidx = pj >> 5, widx = pj & 31;
                    if (qp0) {
                        float rh = rhs[r0 * 32 + hidx];
                        float2 rw = *(const float2*)&rws[r0 * 32 + widx];
                        v00 += rh + rw.x; v01 += rh + rw.y;
                    }
                    if (qp1) {
                        float rh = rhs[r1 * 32 + hidx];
                        float2 rw = *(const float2*)&rws[r1 * 32 + widx];
                        v10 += rh + rw.x; v11 += rh + rw.y;
                    }
                }
                sc[nt][0] = v00; sc[nt][1] = v01;
                sc[nt][2] = v10; sc[nt][3] = v11;
                tm0 = fmaxf(tm0, fmaxf(v00, v01));
                tm1 = fmaxf(tm1, fmaxf(v10, v11));
            }
            tm0 = fmaxf(tm0, __shfl_xor_sync(0xffffffffu, tm0, 1));
            tm0 = fmaxf(tm0, __shfl_xor_sync(0xffffffffu, tm0, 2));
            tm1 = fmaxf(tm1, __shfl_xor_sync(0xffffffffu, tm1, 1));
            tm1 = fmaxf(tm1, __shfl_xor_sync(0xffffffffu, tm1, 2));

            float nm0 = fmaxf(m0r, tm0), nm1 = fmaxf(m1r, tm1);
            float s0 = __expf(m0r - nm0), s1 = __expf(m1r - nm1);
            float sum0 = 0.f, sum1 = 0.f;
#pragma unroll
            for (int nt = 0; nt < 8; ++nt) {
#pragma unroll
                for (int e = 0; e < 2; ++e) {
                    float p0 = __expf(sc[nt][e] - nm0);
                    float p1 = __expf(sc[nt][2 + e] - nm1);
                    sum0 += p0; sum1 += p1;
                    sc[nt][e] = f2tff(p0);
                    sc[nt][2 + e] = f2tff(p1);
                }
            }
            sum0 += __shfl_xor_sync(0xffffffffu, sum0, 1);
            sum0 += __shfl_xor_sync(0xffffffffu, sum0, 2);
            sum1 += __shfl_xor_sync(0xffffffffu, sum1, 1);
            sum1 += __shfl_xor_sync(0xffffffffu, sum1, 2);
            l0r = l0r * s0 + sum0; m0r = nm0;
            l1r = l1r * s1 + sum1; m1r = nm1;

#pragma unroll
            for (int nt = 0; nt < 8; ++nt) {
                oc[nt][0] *= s0; oc[nt][1] *= s0;
                oc[nt][2] *= s1; oc[nt][3] *= s1;
            }

#pragma unroll
            for (int ks = 0; ks < 8; ++ks) {
                float x0 = __shfl_sync(0xffffffffu, sc[ks][0], srcA);
                float x1 = __shfl_sync(0xffffffffu, sc[ks][1], srcA);
                float x2 = __shfl_sync(0xffffffffu, sc[ks][2], srcA);
                float x3 = __shfl_sync(0xffffffffu, sc[ks][3], srcA);
                float y0 = __shfl_sync(0xffffffffu, sc[ks][0], srcB);
                float y1 = __shfl_sync(0xffffffffu, sc[ks][1], srcB);
                float y2 = __shfl_sync(0xffffffffu, sc[ks][2], srcB);
                float y3 = __shfl_sync(0xffffffffu, sc[ks][3], srcB);
                unsigned a[4];
                a[0] = __float_as_uint(odd ? x1 : x0);
                a[1] = __float_as_uint(odd ? x3 : x2);
                a[2] = __float_as_uint(odd ? y1 : y0);
                a[3] = __float_as_uint(odd ? y3 : y2);
#pragma unroll
                for (int nt = 0; nt < 8; ++nt) {
                    unsigned bb[2];
                    int dcol = nt * 8 + g;
                    bb[0] = Vu[(ks * 8 + tig    ) * 72 + dcol];
                    bb[1] = Vu[(ks * 8 + tig + 4) * 72 + dcol];
                    mma8(oc[nt], a, bb);
                }
            }
        }
        __syncthreads();
    }

    {
        float inv0 = (qg0 < NSEQ) ? (1.f / l0r) : 0.f;
        float inv1 = (qg1 < NSEQ) ? (1.f / l1r) : 0.f;
#pragma unroll
        for (int nt = 0; nt < 8; ++nt) {
            int col = nt * 8 + tig * 2;
            if (qg0 < NSEQ) {
                float2 v = make_float2(f2tff(oc[nt][0] * inv0), f2tff(oc[nt][1] * inv0));
                *(float2*)(g_ctx + ((size_t)b * NSEQ + qg0) * C_DIM + head * HD + col) = v;
            }
            if (qg1 < NSEQ) {
                float2 v = make_float2(f2tff(oc[nt][2] * inv1), f2tff(oc[nt][3] * inv1));
                *(float2*)(g_ctx + ((size_t)b * NSEQ + qg1) * C_DIM + head * HD + col) = v;
            }
        }
    }
}

// ---------------------------------------------------------------------------
// K4: output projection GEMM, BK=32, 2-stage cp.async, dynamic smem.
// ---------------------------------------------------------------------------
__global__ __launch_bounds__(256) void proj_mma_kernel(
    const float* __restrict__ bias, float* __restrict__ out)
{
    extern __shared__ float dynsm[];
    float* Asb = dynsm;
    float* Bsb = dynsm + 2 * A_STG;

    const int m0 = blockIdx.y * 128;
    const int n0 = blockIdx.x * 128;
    const int tid = threadIdx.x;
    const int wid = tid >> 5, lane = tid & 31;
    const int g = lane >> 2, tig = lane & 3;
    const int wm = wid >> 1, wn = wid & 1;

    const int aRow = tid >> 1;
    const int aK   = (tid & 1) * 16;
    const int am   = m0 + aRow;
    const bool av  = (am < MROWS);
    const float* arp = g_ctx + (size_t)(av ? am : 0) * C_DIM;

    const int bk = tid >> 5;
    const int bn = (tid & 31) * 4;

    float c[2][8][4];
#pragma unroll
    for (int mt = 0; mt < 2; ++mt)
#pragma unroll
        for (int nt = 0; nt < 8; ++nt)
#pragma unroll
            for (int j = 0; j < 4; ++j) c[mt][nt][j] = 0.f;

    auto load_stage = [&](int s, int k0) {
        unsigned ad = smem_u32(&Asb[s * A_STG + aRow * A_LD + aK]);
        unsigned bd = smem_u32(&Bsb[s * B_STG + bk * B_LD + bn]);
#pragma unroll
        for (int i = 0; i < 4; ++i)
            cpasync16(ad + 16 * i, arp + k0 + aK + 4 * i, av);
#pragma unroll
        for (int i = 0; i < 4; ++i)
            cpasync16(bd + (8 * i) * B_LD * 4,
                      g_wp + (size_t)(k0 + bk + 8 * i) * C_DIM + n0 + bn, true);
        CP_COMMIT();
    };

    const int NKT = C_DIM / 32;
    load_stage(0, 0);

    for (int kt = 0; kt < NKT; ++kt) {
        int s = kt & 1;
        if (kt + 1 < NKT) { load_stage(s ^ 1, (kt + 1) * 32); CP_WAIT(1); }
        else              { CP_WAIT(0); }
        __syncthreads();

        const unsigned* Au = (const unsigned*)(Asb + s * A_STG);
        const unsigned* Bu = (const unsigned*)(Bsb + s * B_STG);
#pragma unroll
        for (int ks = 0; ks < 4; ++ks) {
            unsigned a[2][4];
#pragma unroll
            for (int mt = 0; mt < 2; ++mt) {
                int mr = wm * 32 + mt * 16;
                a[mt][0] = Au[(mr + g    ) * A_LD + ks * 8 + tig];
                a[mt][1] = Au[(mr + g + 8) * A_LD + ks * 8 + tig];
                a[mt][2] = Au[(mr + g    ) * A_LD + ks * 8 + tig + 4];
                a[mt][3] = Au[(mr + g + 8) * A_LD + ks * 8 + tig + 4];
            }
            unsigned b[8][2];
#pragma unroll
            for (int nt = 0; nt < 8; ++nt) {
                int nc = wn * 64 + nt * 8 + g;
                b[nt][0] = Bu[(ks * 8 + tig    ) * B_LD + nc];
                b[nt][1] = Bu[(ks * 8 + tig + 4) * B_LD + nc];
            }
#pragma unroll
            for (int mt = 0; mt < 2; ++mt)
#pragma unroll
                for (int nt = 0; nt < 8; ++nt) mma8(c[mt][nt], a[mt], b[nt]);
        }
        __syncthreads();
    }

#pragma unroll
    for (int nt = 0; nt < 8; ++nt) {
        int col = n0 + wn * 64 + nt * 8 + tig * 2;
        float b0v = bias[col], b1v = bias[col + 1];
#pragma unroll
        for (int mt = 0; mt < 2; ++mt) {
#pragma unroll
            for (int h = 0; h < 2; ++h) {
                int m = m0 + wm * 32 + mt * 16 + g + h * 8;
                if (m >= MROWS) continue;
                int bb = m / NSEQ, nn = m % NSEQ;
                float* dst = (nn < NT)
                    ? (out + XOUT_ELEMS + ((size_t)bb * NT + nn) * C_DIM)
                    : (out + ((size_t)bb * HW + (nn - NT)) * C_DIM);
                float2 v;
                v.x = c[mt][nt][h * 2 + 0] + b0v;
                v.y = c[mt][nt][h * 2 + 1] + b1v;
                *(float2*)(dst + col) = v;
            }
        }
    }
}

// ---------------------------------------------------------------------------
extern "C" void kernel_launch(void* const* d_in, const int* in_sizes, int n_in,
                              void* d_out, int out_size)
{
    const float* x      = (const float*)d_in[0];
    const float* vp     = (const float*)d_in[1];
    const float* qkv_w  = (const float*)d_in[2];
    const float* qkv_b  = (const float*)d_in[3];
    const float* proj_w = (const float*)d_in[4];
    const float* proj_b = (const float*)d_in[5];
    const float* rph    = (const float*)d_in[6];
    const float* rpw    = (const float*)d_in[7];
    float* out = (float*)d_out;

    (void)in_sizes; (void)n_in; (void)out_size;

    cudaFuncSetAttribute(qkv_mma_kernel,
                         cudaFuncAttributeMaxDynamicSharedMemorySize,
                         GEMM_SM_BYTES);
    cudaFuncSetAttribute(proj_mma_kernel,
                         cudaFuncAttributeMaxDynamicSharedMemorySize,
                         GEMM_SM_BYTES);
    cudaFuncSetAttribute(attn_mma_kernel,
                         cudaFuncAttributeMaxDynamicSharedMemorySize,
                         ATT_SM_BYTES);

    prep_xs_kernel<<<1184, 256>>>(x, vp);
    prep_w_kernel<<<1184, 256>>>(qkv_w, proj_w);
    qkv_mma_kernel<<<dim3(QKV_N / 128, (MROWS + 127) / 128), 256, GEMM_SM_BYTES>>>(qkv_b);
    rel_kernel<<<dim3(32, BHN / 4, 2), 256>>>(rph, rpw);
    attn_mma_kernel<<<dim3((NSEQ + 127) / 128, BHN), 256, ATT_SM_BYTES>>>();
    proj_mma_kernel<<<dim3(C_DIM / 128, (MROWS + 127) / 128), 256, GEMM_SM_BYTES>>>(proj_b, out);
}